// round 7
// baseline (speedup 1.0000x reference)
#include <cuda_runtime.h>
#include <cuda_fp16.h>
#include <cuda_bf16.h>
#include <cstdint>
#include <cstddef>

// Problem shape (fixed by the dataset)
#define BB 4096   // batch rows
#define NN 8192   // memory slots
#define WW 64     // key width

// ---------------------------------------------------------------------------
// Scratch (device globals — no allocations allowed)
// ---------------------------------------------------------------------------
__device__ __nv_bfloat16 g_kb[(size_t)BB * WW];  // bf16(k * escale), SW128-preswizzled
__device__ __nv_bfloat16 g_mb[(size_t)NN * WW];  // bf16(mem * mscale), SW128-preswizzled
__device__ __half        g_e[(size_t)BB * NN];   // exp(beta*sim) scratch, fp16 (64 MB)

#define SW128(x) ((x) ^ (((x) >> 3) & 0x70))

__device__ __forceinline__ uint32_t smem_u32(const void* p) {
    uint32_t a;
    asm("{ .reg .u64 t; cvta.to.shared.u64 t, %1; cvt.u32.u64 %0, t; }"
        : "=r"(a) : "l"(p));
    return a;
}

// ---------------------------------------------------------------------------
// Kernel 1: per-row scale factors folded into bf16 operands (pre-swizzled).
//   k rows:  escale = beta * (1/max(||k||,1e-12)) * (1/max(||k_n||,1e-8))
//   mem rows: mscale = 1/max(||mem||,1e-8)
// One warp per row; lane handles cols (2*lane, 2*lane+1).
// ---------------------------------------------------------------------------
__global__ void prep_kernel(const float* __restrict__ K,
                            const float* __restrict__ beta,
                            const float* __restrict__ M)
{
    int w    = (blockIdx.x * blockDim.x + threadIdx.x) >> 5;
    int lane = threadIdx.x & 31;
    if (w >= BB + NN) return;

    bool is_k = (w < BB);
    int  row  = is_k ? w : (w - BB);
    const float* src = (is_k ? K : M) + (size_t)row * WW;

    float x0 = src[2 * lane];
    float x1 = src[2 * lane + 1];
    float ss = x0 * x0 + x1 * x1;
    #pragma unroll
    for (int o = 16; o; o >>= 1) ss += __shfl_xor_sync(0xFFFFFFFFu, ss, o);

    float nrm = sqrtf(ss);
    float sc;
    if (is_k) {
        float a  = 1.0f / fmaxf(nrm, 1e-12f);
        float n2 = nrm * a;                    // ||k_n||
        float b2 = 1.0f / fmaxf(n2, 1e-8f);
        sc = beta[row] * a * b2;
    } else {
        sc = 1.0f / fmaxf(nrm, 1e-8f);
    }

    // Pre-swizzled bf16x2 store: row stride 128B, swizzle permutes 16B units
    // inside each 8-row (1024B) block; a 4B store stays inside one 16B unit.
    uint32_t off = (uint32_t)(row & 7) * 128 + 4 * lane;
    uint32_t sw  = SW128(off);
    char* base = (char*)(is_k ? g_kb : g_mb) + (size_t)(row & ~7) * 128;
    __nv_bfloat162 v = __floats2bfloat162_rn(x0 * sc, x1 * sc);
    *(__nv_bfloat162*)(base + sw) = v;
}

// ---------------------------------------------------------------------------
// Kernel 2: bf16 tensor-core GEMM (mma.sync m16n8k16) + exp epilogue.
//   CTA tile 128x128, K=64. 8 warps in 2(M)x4(N); warp tile 64x32.
//   Operands arrive SW128-preswizzled -> straight 16KB G->S copies, and
//   ldmatrix row addresses recompute the same swizzle (conflict-free).
//   e[b][n] = exp(sim_scaled) stored fp16.
// ---------------------------------------------------------------------------
struct __align__(1024) GemmSmem {
    __nv_bfloat16 A[128 * 64];   // 16 KB
    __nv_bfloat16 B[128 * 64];   // 16 KB
};

// Swizzled byte address of element (row, kbyte) in a tile (row stride 128B).
__device__ __forceinline__ uint32_t tile_addr(uint32_t base, int row, int kbyte) {
    return base + (uint32_t)(row & ~7) * 128 + SW128((uint32_t)(row & 7) * 128 + kbyte);
}

__global__ __launch_bounds__(256) void gemm_exp_kernel()
{
    __shared__ GemmSmem smem;
    int tid  = threadIdx.x;
    int wid  = tid >> 5;
    int lane = tid & 31;
    int n0   = blockIdx.x << 7;
    int m0   = blockIdx.y << 7;

    // Copy pre-swizzled tiles: 16KB each = 1024 uint4 = 256 threads x 4.
    const uint4* gA = (const uint4*)((const char*)g_kb + (size_t)m0 * 128);
    const uint4* gB = (const uint4*)((const char*)g_mb + (size_t)n0 * 128);
    uint4* sA = (uint4*)smem.A;
    uint4* sB = (uint4*)smem.B;
    #pragma unroll
    for (int i = 0; i < 4; i++) {
        int idx = tid + 256 * i;
        sA[idx] = gA[idx];
        sB[idx] = gB[idx];
    }
    __syncthreads();

    uint32_t baseA = smem_u32(smem.A);
    uint32_t baseB = smem_u32(smem.B);

    int warp_m = wid >> 2;           // 0..1 -> 64 rows
    int warp_n = wid & 3;            // 0..3 -> 32 cols
    int m_base = warp_m * 64;
    int n_base = warp_n * 32;

    float acc[4][4][4];              // [mg][ng][frag]
    #pragma unroll
    for (int a = 0; a < 4; a++)
        #pragma unroll
        for (int b = 0; b < 4; b++)
            #pragma unroll
            for (int c = 0; c < 4; c++) acc[a][b][c] = 0.0f;

    #pragma unroll
    for (int ks = 0; ks < 4; ks++) {     // K = 4 x 16
        int k0 = ks * 16;

        // A fragments: 4 x ldmatrix.x4 (m16 x k16 each)
        uint32_t a[4][4];
        #pragma unroll
        for (int mg = 0; mg < 4; mg++) {
            int r  = m_base + mg * 16 + (lane & 15);
            int kb = (k0 + ((lane >> 4) << 3)) * 2;
            uint32_t addr = tile_addr(baseA, r, kb);
            asm volatile("ldmatrix.sync.aligned.m8n8.x4.shared.b16 {%0,%1,%2,%3}, [%4];"
                         : "=r"(a[mg][0]), "=r"(a[mg][1]), "=r"(a[mg][2]), "=r"(a[mg][3])
                         : "r"(addr));
        }
        // B fragments: 2 x ldmatrix.x4, each covers two n8 groups x k16.
        // lanes 0-7: n+0..7 @klo | 8-15: n+0..7 @khi | 16-23: n+8..15 @klo | 24-31: @khi
        uint32_t b[2][4];
        #pragma unroll
        for (int ngp = 0; ngp < 2; ngp++) {
            int n  = n_base + ngp * 16 + (lane & 7) + ((lane >> 4) << 3);
            int kb = (k0 + (((lane >> 3) & 1) << 3)) * 2;
            uint32_t addr = tile_addr(baseB, n, kb);
            asm volatile("ldmatrix.sync.aligned.m8n8.x4.shared.b16 {%0,%1,%2,%3}, [%4];"
                         : "=r"(b[ngp][0]), "=r"(b[ngp][1]), "=r"(b[ngp][2]), "=r"(b[ngp][3])
                         : "r"(addr));
        }
        // MMAs
        #pragma unroll
        for (int mg = 0; mg < 4; mg++)
            #pragma unroll
            for (int ng = 0; ng < 4; ng++) {
                int ngp = ng >> 1, sel = (ng & 1) * 2;
                asm volatile(
                    "mma.sync.aligned.m16n8k16.row.col.f32.bf16.bf16.f32 "
                    "{%0,%1,%2,%3}, {%4,%5,%6,%7}, {%8,%9}, {%0,%1,%2,%3};"
                    : "+f"(acc[mg][ng][0]), "+f"(acc[mg][ng][1]),
                      "+f"(acc[mg][ng][2]), "+f"(acc[mg][ng][3])
                    : "r"(a[mg][0]), "r"(a[mg][1]), "r"(a[mg][2]), "r"(a[mg][3]),
                      "r"(b[ngp][sel]), "r"(b[ngp][sel + 1]));
            }
    }

    // Epilogue: exp -> fp16 g_e. Fragment (m16n8): lane holds
    // rows groupr & groupr+8, cols 2*(lane&3), +1.
    int groupr = lane >> 2;
    int cpair  = (lane & 3) << 1;
    #pragma unroll
    for (int mg = 0; mg < 4; mg++) {
        #pragma unroll
        for (int ng = 0; ng < 4; ng++) {
            int col  = n0 + n_base + ng * 8 + cpair;
            int row0 = m0 + m_base + mg * 16 + groupr;
            float e0 = __expf(acc[mg][ng][0]);
            float e1 = __expf(acc[mg][ng][1]);
            float e2 = __expf(acc[mg][ng][2]);
            float e3 = __expf(acc[mg][ng][3]);
            *(__half2*)(g_e + (size_t)row0 * NN + col)       = __floats2half2_rn(e0, e1);
            *(__half2*)(g_e + (size_t)(row0 + 8) * NN + col) = __floats2half2_rn(e2, e3);
        }
    }
}

// ---------------------------------------------------------------------------
// Kernel 3: per-row finish. One CTA (256 threads) per batch row.
//   Z from the fp16 e row (deterministic fixed-order sum; error ~3e-6 on Z,
//   negligible at the output). Then gate with prev, 3-tap shift, pow,
//   renormalize.
// ---------------------------------------------------------------------------
#define FIN_SMEM ((NN + 64) * 4)   // 33 KB: under the 48 KB default

__device__ __forceinline__ float block_reduce_sum(float v, float* red)
{
    int tid = threadIdx.x;
    #pragma unroll
    for (int o = 16; o; o >>= 1) v += __shfl_xor_sync(0xFFFFFFFFu, v, o);
    if ((tid & 31) == 0) red[tid >> 5] = v;
    __syncthreads();
    if (tid < 32) {
        float x = (tid < 8) ? red[tid] : 0.0f;   // 8 warps
        #pragma unroll
        for (int o = 4; o; o >>= 1) x += __shfl_xor_sync(0xFFFFFFFFu, x, o);
        if (tid == 0) red[16] = x;               // disjoint slot
    }
    __syncthreads();
    return red[16];
}

__global__ __launch_bounds__(256) void finish_kernel(
    const float* __restrict__ prev,
    const float* __restrict__ g,
    const float* __restrict__ s,
    const float* __restrict__ gamma,
    float* __restrict__ out)
{
    extern __shared__ float sm[];
    float* buf = sm;             // e row, then gated row [8192]
    float* red = sm + NN;        // reduction scratch

    int b   = blockIdx.x;
    int tid = threadIdx.x;

    // Pass A: load e (half2), stage to SMEM, accumulate Z.
    const __half2* e2 = (const __half2*)g_e + (size_t)b * (NN / 2);
    float z = 0.0f;
    #pragma unroll
    for (int j = 0; j < 16; j++) {
        int i = tid + 256 * j;
        float2 v = __half22float2(e2[i]);
        *(float2*)&buf[2 * i] = v;
        z += v.x + v.y;
    }
    float Z = block_reduce_sum(z, red);

    float gb = g[b];
    float gm = gamma[b];
    float s0 = s[3 * b], s1 = s[3 * b + 1], s2 = s[3 * b + 2];
    float mx  = fmaxf(s0, fmaxf(s1, s2));
    float es0 = __expf(s0 - mx), es1 = __expf(s1 - mx), es2 = __expf(s2 - mx);
    float inv3 = 1.0f / (es0 + es1 + es2);
    float ss0 = es0 * inv3, ss1 = es1 * inv3, ss2 = es2 * inv3;

    float gcw = gb / Z;          // g * (e/Z)
    float om  = 1.0f - gb;

    // Pass B: gate with prev (each thread rewrites its own slots; the
    // block_reduce's trailing barrier ordered pass A's stores).
    const float2* p2 = (const float2*)(prev + (size_t)b * NN);
    #pragma unroll
    for (int j = 0; j < 16; j++) {
        int i = tid + 256 * j;
        float2 v = *(float2*)&buf[2 * i];
        float2 p = p2[i];
        v.x = gcw * v.x + om * p.x;
        v.y = gcw * v.y + om * p.y;
        *(float2*)&buf[2 * i] = v;
    }
    __syncthreads();

    // Pass C: 3-tap non-circular shift + pow into registers, accumulate S.
    float r[32];
    float ssum = 0.0f;
    #pragma unroll
    for (int j = 0; j < 32; j++) {
        int i = tid + 256 * j;
        float left  = (i > 0)      ? buf[i - 1] : 0.0f;
        float mid   = buf[i];
        float right = (i < NN - 1) ? buf[i + 1] : 0.0f;
        float sh = ss0 * left + ss1 * mid + ss2 * right;
        float sp = __powf(sh, gm);
        r[j] = sp;
        ssum += sp;
    }
    float S  = block_reduce_sum(ssum, red);
    float sc = 1.0f / (S + 1e-8f);

    // Pass D: scaled store (coalesced).
    float* orow = out + (size_t)b * NN;
    #pragma unroll
    for (int j = 0; j < 32; j++)
        orow[tid + 256 * j] = r[j] * sc;
}

// ---------------------------------------------------------------------------
// Launch. Inputs (metadata order): k, beta, g, s, gamma, prev_weights, memory
// ---------------------------------------------------------------------------
extern "C" void kernel_launch(void* const* d_in, const int* in_sizes, int n_in,
                              void* d_out, int out_size)
{
    const float* K    = (const float*)d_in[0];
    const float* beta = (const float*)d_in[1];
    const float* g    = (const float*)d_in[2];
    const float* s    = (const float*)d_in[3];
    const float* gam  = (const float*)d_in[4];
    const float* prev = (const float*)d_in[5];
    const float* M    = (const float*)d_in[6];
    float* out = (float*)d_out;

    // 4096 + 8192 rows, one warp each, 8 warps per block.
    prep_kernel<<<(BB + NN) / 8, 256>>>(K, beta, M);

    // 64 N-tiles x 32 M-tiles, 256 threads.
    gemm_exp_kernel<<<dim3(NN / 128, BB / 128), 256>>>();

    finish_kernel<<<BB, 256, FIN_SMEM>>>(prev, g, s, gam, out);
}

// round 8
// speedup vs baseline: 1.0645x; 1.0645x over previous
#include <cuda_runtime.h>
#include <cuda_fp16.h>
#include <cuda_bf16.h>
#include <cstdint>
#include <cstddef>

// Problem shape (fixed by the dataset)
#define BB 4096   // batch rows
#define NN 8192   // memory slots
#define WW 64     // key width

#define QSCALE 124.0f
#define QINV   (1.0f / 124.0f)

// ---------------------------------------------------------------------------
// Scratch (device globals — no allocations allowed)
// ---------------------------------------------------------------------------
__device__ __nv_bfloat16 g_kb[(size_t)BB * WW];  // bf16(k * escale), SW128-preswizzled
__device__ __nv_bfloat16 g_mb[(size_t)NN * WW];  // bf16(mem * mscale), SW128-preswizzled
__device__ char          g_q[(size_t)BB * NN];   // int8 quantized beta*sim (32 MB)

#define SW128(x) ((x) ^ (((x) >> 3) & 0x70))

__device__ __forceinline__ uint32_t smem_u32(const void* p) {
    uint32_t a;
    asm("{ .reg .u64 t; cvta.to.shared.u64 t, %1; cvt.u32.u64 %0, t; }"
        : "=r"(a) : "l"(p));
    return a;
}

__device__ __forceinline__ int q8(float x) {
    return __float2int_rn(fminf(fmaxf(x * QSCALE, -127.0f), 127.0f));
}

// ---------------------------------------------------------------------------
// Kernel 1: per-row scale factors folded into bf16 operands (pre-swizzled).
//   k rows:  escale = beta * (1/max(||k||,1e-12)) * (1/max(||k_n||,1e-8))
//   mem rows: mscale = 1/max(||mem||,1e-8)
// One warp per row; lane handles cols (2*lane, 2*lane+1).
// ---------------------------------------------------------------------------
__global__ void prep_kernel(const float* __restrict__ K,
                            const float* __restrict__ beta,
                            const float* __restrict__ M)
{
    int w    = (blockIdx.x * blockDim.x + threadIdx.x) >> 5;
    int lane = threadIdx.x & 31;
    if (w >= BB + NN) return;

    bool is_k = (w < BB);
    int  row  = is_k ? w : (w - BB);
    const float* src = (is_k ? K : M) + (size_t)row * WW;

    float x0 = src[2 * lane];
    float x1 = src[2 * lane + 1];
    float ss = x0 * x0 + x1 * x1;
    #pragma unroll
    for (int o = 16; o; o >>= 1) ss += __shfl_xor_sync(0xFFFFFFFFu, ss, o);

    float nrm = sqrtf(ss);
    float sc;
    if (is_k) {
        float a  = 1.0f / fmaxf(nrm, 1e-12f);
        float n2 = nrm * a;                    // ||k_n||
        float b2 = 1.0f / fmaxf(n2, 1e-8f);
        sc = beta[row] * a * b2;
    } else {
        sc = 1.0f / fmaxf(nrm, 1e-8f);
    }

    // Pre-swizzled bf16x2 store: row stride 128B, swizzle permutes 16B units
    // inside each 8-row (1024B) block; a 4B store stays inside one 16B unit.
    uint32_t off = (uint32_t)(row & 7) * 128 + 4 * lane;
    uint32_t sw  = SW128(off);
    char* base = (char*)(is_k ? g_kb : g_mb) + (size_t)(row & ~7) * 128;
    __nv_bfloat162 v = __floats2bfloat162_rn(x0 * sc, x1 * sc);
    *(__nv_bfloat162*)(base + sw) = v;
}

// ---------------------------------------------------------------------------
// Kernel 2: bf16 tensor-core GEMM (mma.sync m16n8k16), int8 epilogue.
//   CTA tile 128x128, K=64. 8 warps in 2(M)x4(N); warp tile 64x32.
//   Operands arrive SW128-preswizzled -> straight 16KB G->S copies, and
//   ldmatrix row addresses recompute the same swizzle (conflict-free).
//   Epilogue: quantize sim to int8 via SMEM staging (stride 144B ->
//   fragment rows hit distinct bank groups), then coalesced uint4 flush.
// ---------------------------------------------------------------------------
#define ESTRIDE 144   // bytes per staged row (16B-aligned; 36 words, mod32=4)

union __align__(1024) GemmSmem {
    struct {
        __nv_bfloat16 A[128 * 64];   // 16 KB
        __nv_bfloat16 B[128 * 64];   // 16 KB
    } in;
    char e[128 * ESTRIDE];           // 18 KB staging for the int8 tile
};

// Swizzled byte address of element (row, kbyte) in a tile (row stride 128B).
__device__ __forceinline__ uint32_t tile_addr(uint32_t base, int row, int kbyte) {
    return base + (uint32_t)(row & ~7) * 128 + SW128((uint32_t)(row & 7) * 128 + kbyte);
}

__global__ __launch_bounds__(256) void gemm_q_kernel()
{
    __shared__ GemmSmem smem;
    int tid  = threadIdx.x;
    int wid  = tid >> 5;
    int lane = tid & 31;
    int n0   = blockIdx.x << 7;
    int m0   = blockIdx.y << 7;

    // Copy pre-swizzled tiles: 16KB each = 1024 uint4 = 256 threads x 4.
    const uint4* gA = (const uint4*)((const char*)g_kb + (size_t)m0 * 128);
    const uint4* gB = (const uint4*)((const char*)g_mb + (size_t)n0 * 128);
    uint4* sA = (uint4*)smem.in.A;
    uint4* sB = (uint4*)smem.in.B;
    #pragma unroll
    for (int i = 0; i < 4; i++) {
        int idx = tid + 256 * i;
        sA[idx] = gA[idx];
        sB[idx] = gB[idx];
    }
    __syncthreads();

    uint32_t baseA = smem_u32(smem.in.A);
    uint32_t baseB = smem_u32(smem.in.B);

    int warp_m = wid >> 2;           // 0..1 -> 64 rows
    int warp_n = wid & 3;            // 0..3 -> 32 cols
    int m_base = warp_m * 64;
    int n_base = warp_n * 32;

    float acc[4][4][4];              // [mg][ng][frag]
    #pragma unroll
    for (int a = 0; a < 4; a++)
        #pragma unroll
        for (int b = 0; b < 4; b++)
            #pragma unroll
            for (int c = 0; c < 4; c++) acc[a][b][c] = 0.0f;

    #pragma unroll
    for (int ks = 0; ks < 4; ks++) {     // K = 4 x 16
        int k0 = ks * 16;

        // A fragments: 4 x ldmatrix.x4 (m16 x k16 each)
        uint32_t a[4][4];
        #pragma unroll
        for (int mg = 0; mg < 4; mg++) {
            int r  = m_base + mg * 16 + (lane & 15);
            int kb = (k0 + ((lane >> 4) << 3)) * 2;
            uint32_t addr = tile_addr(baseA, r, kb);
            asm volatile("ldmatrix.sync.aligned.m8n8.x4.shared.b16 {%0,%1,%2,%3}, [%4];"
                         : "=r"(a[mg][0]), "=r"(a[mg][1]), "=r"(a[mg][2]), "=r"(a[mg][3])
                         : "r"(addr));
        }
        // B fragments: 2 x ldmatrix.x4, each covers two n8 groups x k16.
        uint32_t b[2][4];
        #pragma unroll
        for (int ngp = 0; ngp < 2; ngp++) {
            int n  = n_base + ngp * 16 + (lane & 7) + ((lane >> 4) << 3);
            int kb = (k0 + (((lane >> 3) & 1) << 3)) * 2;
            uint32_t addr = tile_addr(baseB, n, kb);
            asm volatile("ldmatrix.sync.aligned.m8n8.x4.shared.b16 {%0,%1,%2,%3}, [%4];"
                         : "=r"(b[ngp][0]), "=r"(b[ngp][1]), "=r"(b[ngp][2]), "=r"(b[ngp][3])
                         : "r"(addr));
        }
        // MMAs
        #pragma unroll
        for (int mg = 0; mg < 4; mg++)
            #pragma unroll
            for (int ng = 0; ng < 4; ng++) {
                int ngp = ng >> 1, sel = (ng & 1) * 2;
                asm volatile(
                    "mma.sync.aligned.m16n8k16.row.col.f32.bf16.bf16.f32 "
                    "{%0,%1,%2,%3}, {%4,%5,%6,%7}, {%8,%9}, {%0,%1,%2,%3};"
                    : "+f"(acc[mg][ng][0]), "+f"(acc[mg][ng][1]),
                      "+f"(acc[mg][ng][2]), "+f"(acc[mg][ng][3])
                    : "r"(a[mg][0]), "r"(a[mg][1]), "r"(a[mg][2]), "r"(a[mg][3]),
                      "r"(b[ngp][sel]), "r"(b[ngp][sel + 1]));
            }
    }

    // All ldmatrix reads done before the union is repurposed.
    __syncthreads();

    // Stage quantized int8 tile. Fragment (m16n8): lane -> rows groupr &
    // groupr+8, cols 2*(lane&3), +1 (adjacent -> one 2-byte store each).
    int groupr = lane >> 2;
    int cpair  = (lane & 3) << 1;
    #pragma unroll
    for (int mg = 0; mg < 4; mg++) {
        #pragma unroll
        for (int ng = 0; ng < 4; ng++) {
            int r = m_base + mg * 16 + groupr;
            int c = n_base + ng * 8 + cpair;
            int q0 = q8(acc[mg][ng][0]);
            int q1 = q8(acc[mg][ng][1]);
            int q2 = q8(acc[mg][ng][2]);
            int q3 = q8(acc[mg][ng][3]);
            *(short*)&smem.e[r * ESTRIDE + c] =
                (short)((q0 & 0xFF) | ((q1 & 0xFF) << 8));
            *(short*)&smem.e[(r + 8) * ESTRIDE + c] =
                (short)((q2 & 0xFF) | ((q3 & 0xFF) << 8));
        }
    }
    __syncthreads();

    // Coalesced flush: 128 rows x 128B = 1024 uint4 = 256 threads x 4.
    #pragma unroll
    for (int i = 0; i < 4; i++) {
        int gi = tid + 256 * i;
        int r  = gi >> 3;
        int c  = gi & 7;
        uint4 v = *(const uint4*)&smem.e[r * ESTRIDE + c * 16];
        *(uint4*)(g_q + (size_t)(m0 + r) * NN + n0 + c * 16) = v;
    }
}

// ---------------------------------------------------------------------------
// Kernel 3: per-row finish. One CTA (256 threads) per batch row.
//   Dequant int8 -> e = exp(q/QSCALE) (MUFU hidden under DRAM streaming);
//   Z summed from the SAME quantized values the weights use, so softmax
//   renormalization cancels most quantization error. Then gate with prev,
//   3-tap shift, pow, renormalize.
// ---------------------------------------------------------------------------
#define FIN_SMEM ((NN + 64) * 4)   // 33 KB: under the 48 KB default

__device__ __forceinline__ float block_reduce_sum(float v, float* red)
{
    int tid = threadIdx.x;
    #pragma unroll
    for (int o = 16; o; o >>= 1) v += __shfl_xor_sync(0xFFFFFFFFu, v, o);
    if ((tid & 31) == 0) red[tid >> 5] = v;
    __syncthreads();
    if (tid < 32) {
        float x = (tid < 8) ? red[tid] : 0.0f;   // 8 warps
        #pragma unroll
        for (int o = 4; o; o >>= 1) x += __shfl_xor_sync(0xFFFFFFFFu, x, o);
        if (tid == 0) red[16] = x;               // disjoint slot
    }
    __syncthreads();
    return red[16];
}

__global__ __launch_bounds__(256) void finish_kernel(
    const float* __restrict__ prev,
    const float* __restrict__ g,
    const float* __restrict__ s,
    const float* __restrict__ gamma,
    float* __restrict__ out)
{
    extern __shared__ float sm[];
    float* buf = sm;             // e row, then gated row [8192]
    float* red = sm + NN;        // reduction scratch

    int b   = blockIdx.x;
    int tid = threadIdx.x;

    // Pass A: load int8 row (uint4 = 16 vals), dequant+exp, stage to SMEM,
    // accumulate Z.
    const uint4* q4 = (const uint4*)(g_q + (size_t)b * NN);
    float z = 0.0f;
    #pragma unroll
    for (int j = 0; j < 2; j++) {
        int i = tid + 256 * j;            // 512 uint4 per row
        uint4 v = q4[i];
        float* dst = &buf[i * 16];
        uint32_t wds[4] = {v.x, v.y, v.z, v.w};
        #pragma unroll
        for (int w = 0; w < 4; w++) {
            uint32_t u = wds[w];
            float e0 = __expf((float)(int)(char)(u)        * QINV);
            float e1 = __expf((float)(int)(char)(u >> 8)   * QINV);
            float e2 = __expf((float)(int)(char)(u >> 16)  * QINV);
            float e3 = __expf((float)(int)(char)(u >> 24)  * QINV);
            dst[4 * w + 0] = e0;
            dst[4 * w + 1] = e1;
            dst[4 * w + 2] = e2;
            dst[4 * w + 3] = e3;
            z += (e0 + e1) + (e2 + e3);
        }
    }
    float Z = block_reduce_sum(z, red);

    float gb = g[b];
    float gm = gamma[b];
    float s0 = s[3 * b], s1 = s[3 * b + 1], s2 = s[3 * b + 2];
    float mx  = fmaxf(s0, fmaxf(s1, s2));
    float es0 = __expf(s0 - mx), es1 = __expf(s1 - mx), es2 = __expf(s2 - mx);
    float inv3 = 1.0f / (es0 + es1 + es2);
    float ss0 = es0 * inv3, ss1 = es1 * inv3, ss2 = es2 * inv3;

    float gcw = gb / Z;          // g * (e/Z)
    float om  = 1.0f - gb;

    // Pass B: gate with prev (each thread rewrites its own slots; the
    // block_reduce's trailing barrier ordered pass A's stores).
    const float4* p4 = (const float4*)(prev + (size_t)b * NN);
    #pragma unroll
    for (int j = 0; j < 8; j++) {
        int i = tid + 256 * j;
        float4 v = *(float4*)&buf[4 * i];
        float4 p = p4[i];
        v.x = gcw * v.x + om * p.x;
        v.y = gcw * v.y + om * p.y;
        v.z = gcw * v.z + om * p.z;
        v.w = gcw * v.w + om * p.w;
        *(float4*)&buf[4 * i] = v;
    }
    __syncthreads();

    // Pass C: 3-tap non-circular shift + pow into registers, accumulate S.
    float r[32];
    float ssum = 0.0f;
    #pragma unroll
    for (int j = 0; j < 32; j++) {
        int i = tid + 256 * j;
        float left  = (i > 0)      ? buf[i - 1] : 0.0f;
        float mid   = buf[i];
        float right = (i < NN - 1) ? buf[i + 1] : 0.0f;
        float sh = ss0 * left + ss1 * mid + ss2 * right;
        float sp = __powf(sh, gm);
        r[j] = sp;
        ssum += sp;
    }
    float S  = block_reduce_sum(ssum, red);
    float sc = 1.0f / (S + 1e-8f);

    // Pass D: scaled store (coalesced).
    float* orow = out + (size_t)b * NN;
    #pragma unroll
    for (int j = 0; j < 32; j++)
        orow[tid + 256 * j] = r[j] * sc;
}

// ---------------------------------------------------------------------------
// Launch. Inputs (metadata order): k, beta, g, s, gamma, prev_weights, memory
// ---------------------------------------------------------------------------
extern "C" void kernel_launch(void* const* d_in, const int* in_sizes, int n_in,
                              void* d_out, int out_size)
{
    const float* K    = (const float*)d_in[0];
    const float* beta = (const float*)d_in[1];
    const float* g    = (const float*)d_in[2];
    const float* s    = (const float*)d_in[3];
    const float* gam  = (const float*)d_in[4];
    const float* prev = (const float*)d_in[5];
    const float* M    = (const float*)d_in[6];
    float* out = (float*)d_out;

    // 4096 + 8192 rows, one warp each, 8 warps per block.
    prep_kernel<<<(BB + NN) / 8, 256>>>(K, beta, M);

    // 64 N-tiles x 32 M-tiles, 256 threads.
    gemm_q_kernel<<<dim3(NN / 128, BB / 128), 256>>>();

    finish_kernel<<<BB, 256, FIN_SMEM>>>(prev, g, s, gam, out);
}